// round 4
// baseline (speedup 1.0000x reference)
#include <cuda_runtime.h>
#include <cuda_bf16.h>

#define D_MODEL 4096
#define SHARDS  8

// Scratch (no device mallocs allowed): bias sum + token-dtype flag.
__device__ float g_bsum[D_MODEL];
__device__ int   g_is64;

// Detect whether the token buffer is int64 or int32.
// View as int32: for an int64 buffer (tokens < 50400, little-endian) every odd
// int32 is the zero high-word; for an int32 buffer odd entries are random
// tokens (P(zero) = 1/50400 each). Reads only the first 256 int32 = 1 KB,
// safe under both layouts (int32 buffer is 16 KB).
__global__ void detect_tok_dtype_kernel(const int* __restrict__ x32) {
    if (threadIdx.x == 0 && blockIdx.x == 0) {
        int zeros = 0;
        #pragma unroll 1
        for (int i = 0; i < 128; i++)
            if (x32[2 * i + 1] == 0) zeros++;
        g_is64 = (zeros > 64) ? 1 : 0;
    }
}

// bsum[d] = sum over 8 shard biases. 4096 threads total, trivial.
__global__ void bias_sum_kernel(const float* __restrict__ b) {
    int d = blockIdx.x * blockDim.x + threadIdx.x;
    if (d < D_MODEL) {
        float s = 0.f;
        #pragma unroll
        for (int i = 0; i < SHARDS; i++) s += b[i * D_MODEL + d];
        g_bsum[d] = s;
    }
}

// One block per token: copy W[tok, :] (16 KB) + bsum into out[t, :].
// 256 threads x 4 float4 each = 1024 float4 = 4096 floats. Fully coalesced
// 128B transactions; MLP=4 per thread hides DRAM latency; bsum (16 KB) stays
// L2/L1-resident across all blocks.
__global__ void __launch_bounds__(256) gather_bias_kernel(
    const void* __restrict__ xraw,
    const float* __restrict__ W,
    float* __restrict__ out)
{
    const int t = blockIdx.x;
    long long tok;
    if (g_is64) tok = ((const long long*)xraw)[t];
    else        tok = (long long)((const int*)xraw)[t];

    const float4* __restrict__ src = (const float4*)(W + tok * (long long)D_MODEL);
    float4*       __restrict__ dst = (float4*)(out + (long long)t * D_MODEL);
    const float4* __restrict__ bs  = (const float4*)g_bsum;

    #pragma unroll
    for (int i = 0; i < 4; i++) {
        const int j = threadIdx.x + i * 256;   // 0..1023
        float4 w = src[j];
        float4 v = bs[j];
        w.x += v.x; w.y += v.y; w.z += v.z; w.w += v.w;
        dst[j] = w;
    }
}

extern "C" void kernel_launch(void* const* d_in, const int* in_sizes, int n_in,
                              void* d_out, int out_size) {
    // Bind inputs by element count (robust to metadata ordering):
    //   x: 4096 tokens (int32 or int64), b: 8*4096 = 32768 fp32,
    //   W: 50400*4096 fp32 (the big one).
    const void*  x = nullptr;
    const float* W = nullptr;
    const float* b = nullptr;
    int n_tok = 4096;

    long long w_sz = -1;
    int w_idx = -1;
    for (int i = 0; i < n_in; i++) {
        if ((long long)in_sizes[i] > w_sz) { w_sz = in_sizes[i]; w_idx = i; }
    }
    W = (const float*)d_in[w_idx];
    for (int i = 0; i < n_in; i++) {
        if (i == w_idx) continue;
        if (in_sizes[i] == SHARDS * D_MODEL) b = (const float*)d_in[i];
        else { x = d_in[i]; n_tok = in_sizes[i]; }
    }

    float* out = (float*)d_out;

    detect_tok_dtype_kernel<<<1, 32>>>((const int*)x);
    bias_sum_kernel<<<(D_MODEL + 255) / 256, 256>>>(b);
    gather_bias_kernel<<<n_tok, 256>>>(x, W, out);
}

// round 7
// speedup vs baseline: 1.2797x; 1.2797x over previous
#include <cuda_runtime.h>
#include <cuda_bf16.h>

#define D_MODEL 4096
#define SHARDS  8

// Scratch (no device mallocs allowed): precomputed bias sum.
__device__ float g_bsum[D_MODEL];

// bsum[d] = sum over 8 shard biases. 4096 threads total, tiny.
__global__ void bias_sum_kernel(const float* __restrict__ b) {
    int d = blockIdx.x * blockDim.x + threadIdx.x;
    if (d < D_MODEL) {
        float s = 0.f;
        #pragma unroll
        for (int i = 0; i < SHARDS; i++) s += b[i * D_MODEL + d];
        g_bsum[d] = s;
    }
}

// One block per token: out[t,:] = W[tok,:] + bsum.
// 256 threads x 4 float4 = 4096 floats (16 KB row), fully coalesced 128B
// transactions, MLP=4 per thread.
//
// Token-dtype detection is inlined per block (saves the 15us serial detect
// kernel seen in ncu): viewing x as int32, an int64 buffer (tokens < 50400,
// little-endian) has zero high-words at all odd indices; an int32 buffer has
// random tokens there (P(all four == 0) ~ (1/50400)^4 ~ 1e-19). These 4 words
// are L2/L1-resident after the first block and overlap with the row fetch.
__global__ void __launch_bounds__(256) gather_bias_kernel(
    const int* __restrict__ x32,
    const float* __restrict__ W,
    float* __restrict__ out)
{
    const int t = blockIdx.x;

    const bool is64 = (x32[1] | x32[3] | x32[5] | x32[7]) == 0;
    long long tok;
    if (is64) tok = ((const long long*)x32)[t];
    else      tok = (long long)x32[t];

    const float4* __restrict__ src = (const float4*)(W + tok * (long long)D_MODEL);
    float4*       __restrict__ dst = (float4*)(out + (long long)t * D_MODEL);
    const float4* __restrict__ bs  = (const float4*)g_bsum;

    #pragma unroll
    for (int i = 0; i < 4; i++) {
        const int j = threadIdx.x + i * 256;   // 0..1023
        float4 w = src[j];
        float4 v = bs[j];
        w.x += v.x; w.y += v.y; w.z += v.z; w.w += v.w;
        dst[j] = w;
    }
}

extern "C" void kernel_launch(void* const* d_in, const int* in_sizes, int n_in,
                              void* d_out, int out_size) {
    // Bind inputs by element count (robust to metadata ordering):
    //   x: 4096 tokens (int32 or int64), b: 8*4096 = 32768 fp32,
    //   W: 50400*4096 fp32 (the big one).
    const void*  x = nullptr;
    const float* W = nullptr;
    const float* b = nullptr;
    int n_tok = 4096;

    long long w_sz = -1;
    int w_idx = -1;
    for (int i = 0; i < n_in; i++) {
        if ((long long)in_sizes[i] > w_sz) { w_sz = in_sizes[i]; w_idx = i; }
    }
    W = (const float*)d_in[w_idx];
    for (int i = 0; i < n_in; i++) {
        if (i == w_idx) continue;
        if (in_sizes[i] == SHARDS * D_MODEL) b = (const float*)d_in[i];
        else { x = d_in[i]; n_tok = in_sizes[i]; }
    }

    float* out = (float*)d_out;

    bias_sum_kernel<<<(D_MODEL + 255) / 256, 256>>>(b);
    gather_bias_kernel<<<n_tok, 256>>>((const int*)x, W, out);
}

// round 9
// speedup vs baseline: 1.4867x; 1.1618x over previous
#include <cuda_runtime.h>
#include <cuda_bf16.h>

#define D_MODEL     4096
#define SHARDS      8
#define TOK_PER_BLK 16
#define THREADS     256           // each thread owns one float4 -> chunk = 1024 floats
#define N_CHUNKS    (D_MODEL / (THREADS * 4))   // 4

// Fused: out[t, :] = W[x[t], :] + sum_s b[s, :].
// Block = (column chunk of 1024 floats) x (group of 16 tokens).
// Bias for this thread's float4 is summed once into registers (b is 128 KB,
// L2-resident; 1024 blocks x 32 KB = 32 MB of L2-hit traffic, overlapped).
// W reads / out writes use streaming hints (no reuse) so L1/L2 stay clean.
__global__ void __launch_bounds__(THREADS) fused_gather_kernel(
    const int* __restrict__ x32,
    const float* __restrict__ W,
    const float* __restrict__ b,
    float* __restrict__ out,
    int n_tok)
{
    const int pos = blockIdx.x * (THREADS * 4) + threadIdx.x * 4;  // d-index
    const int t0  = blockIdx.y * TOK_PER_BLK;

    // Per-thread bias sum (one float4) across 8 shards.
    float4 bias = make_float4(0.f, 0.f, 0.f, 0.f);
    #pragma unroll
    for (int s = 0; s < SHARDS; s++) {
        const float4 v = __ldg((const float4*)(b + s * D_MODEL + pos));
        bias.x += v.x; bias.y += v.y; bias.z += v.z; bias.w += v.w;
    }

    // Token-dtype detect (int64 buffers have zero high words at odd int32
    // indices; P(false positive for int32) ~ (1/50400)^4). L1/L2-resident.
    const bool is64 = (x32[1] | x32[3] | x32[5] | x32[7]) == 0;

    // Stage this group's 16 token ids in shared memory (broadcast LDS later).
    __shared__ long long toks[TOK_PER_BLK];
    if (threadIdx.x < TOK_PER_BLK) {
        const int t = t0 + threadIdx.x;
        long long tk = 0;
        if (t < n_tok)
            tk = is64 ? ((const long long*)x32)[t] : (long long)x32[t];
        toks[threadIdx.x] = tk;
    }
    __syncthreads();

    #pragma unroll 4
    for (int i = 0; i < TOK_PER_BLK; i++) {
        const int t = t0 + i;
        if (t >= n_tok) break;
        const float4 w = __ldcs((const float4*)(W + toks[i] * (long long)D_MODEL + pos));
        float4 r;
        r.x = w.x + bias.x; r.y = w.y + bias.y;
        r.z = w.z + bias.z; r.w = w.w + bias.w;
        __stcs((float4*)(out + (long long)t * D_MODEL + pos), r);
    }
}

extern "C" void kernel_launch(void* const* d_in, const int* in_sizes, int n_in,
                              void* d_out, int out_size) {
    // Bind inputs by element count (robust to metadata ordering):
    //   x: 4096 tokens (int32 or int64), b: 8*4096 = 32768 fp32,
    //   W: 50400*4096 fp32 (the big one).
    const void*  x = nullptr;
    const float* W = nullptr;
    const float* b = nullptr;
    int n_tok = 4096;

    long long w_sz = -1;
    int w_idx = -1;
    for (int i = 0; i < n_in; i++) {
        if ((long long)in_sizes[i] > w_sz) { w_sz = in_sizes[i]; w_idx = i; }
    }
    W = (const float*)d_in[w_idx];
    for (int i = 0; i < n_in; i++) {
        if (i == w_idx) continue;
        if (in_sizes[i] == SHARDS * D_MODEL) b = (const float*)d_in[i];
        else { x = d_in[i]; n_tok = in_sizes[i]; }
    }

    float* out = (float*)d_out;

    dim3 grid(N_CHUNKS, (n_tok + TOK_PER_BLK - 1) / TOK_PER_BLK);
    fused_gather_kernel<<<grid, THREADS>>>((const int*)x, W, b, out, n_tok);
}

// round 10
// speedup vs baseline: 1.6176x; 1.0880x over previous
#include <cuda_runtime.h>
#include <cuda_bf16.h>

#define D_MODEL     4096
#define SHARDS      8
#define TOK_PER_BLK 16
#define BATCH       8             // loads in flight per thread before stores
#define THREADS     256           // each thread owns one float4 -> chunk = 1024 floats
#define N_CHUNKS    (D_MODEL / (THREADS * 4))   // 4

// Fused: out[t, :] = W[x[t], :] + sum_s b[s, :].
// Block = (column chunk of 1024 floats) x (group of 16 tokens).
// Two-phase batched mainloop: 8 LDG.128 issued back-to-back (MLP_p1=8),
// then 8 predicated STG.128. No early-exit branch in the loop so ptxas can
// front-batch the loads (the round-7 `break` capped MLP at ~4 and left
// DRAM at 44%).
__global__ void __launch_bounds__(THREADS) fused_gather_kernel(
    const int* __restrict__ x32,
    const float* __restrict__ W,
    const float* __restrict__ b,
    float* __restrict__ out,
    int n_tok)
{
    const int pos = blockIdx.x * (THREADS * 4) + threadIdx.x * 4;  // d-index
    const int t0  = blockIdx.y * TOK_PER_BLK;

    // Per-thread bias sum (one float4) across 8 shards (b is 128 KB, L2-hot).
    float4 bias = make_float4(0.f, 0.f, 0.f, 0.f);
    #pragma unroll
    for (int s = 0; s < SHARDS; s++) {
        const float4 v = __ldg((const float4*)(b + s * D_MODEL + pos));
        bias.x += v.x; bias.y += v.y; bias.z += v.z; bias.w += v.w;
    }

    // Token-dtype detect (int64 buffers have zero high words at odd int32
    // indices; P(false positive for int32) ~ (1/50400)^4). L1/L2-resident.
    const bool is64 = (x32[1] | x32[3] | x32[5] | x32[7]) == 0;

    // Stage this group's 16 token ids in shared memory.
    // Out-of-range tokens clamp to 0 (row 0 is a valid load; store is
    // predicated off below).
    __shared__ long long toks[TOK_PER_BLK];
    if (threadIdx.x < TOK_PER_BLK) {
        const int t = t0 + threadIdx.x;
        long long tk = 0;
        if (t < n_tok)
            tk = is64 ? ((const long long*)x32)[t] : (long long)x32[t];
        toks[threadIdx.x] = tk;
    }
    __syncthreads();

    #pragma unroll
    for (int i0 = 0; i0 < TOK_PER_BLK; i0 += BATCH) {
        float4 w[BATCH];
        // Phase 1: batch all loads (independent -> issued back-to-back).
        #pragma unroll
        for (int k = 0; k < BATCH; k++) {
            w[k] = __ldcs((const float4*)(W + toks[i0 + k] * (long long)D_MODEL + pos));
        }
        // Phase 2: add bias + predicated streaming stores.
        #pragma unroll
        for (int k = 0; k < BATCH; k++) {
            const int t = t0 + i0 + k;
            float4 r;
            r.x = w[k].x + bias.x; r.y = w[k].y + bias.y;
            r.z = w[k].z + bias.z; r.w = w[k].w + bias.w;
            if (t < n_tok)
                __stcs((float4*)(out + (long long)t * D_MODEL + pos), r);
        }
    }
}

extern "C" void kernel_launch(void* const* d_in, const int* in_sizes, int n_in,
                              void* d_out, int out_size) {
    // Bind inputs by element count (robust to metadata ordering):
    //   x: 4096 tokens (int32 or int64), b: 8*4096 = 32768 fp32,
    //   W: 50400*4096 fp32 (the big one).
    const void*  x = nullptr;
    const float* W = nullptr;
    const float* b = nullptr;
    int n_tok = 4096;

    long long w_sz = -1;
    int w_idx = -1;
    for (int i = 0; i < n_in; i++) {
        if ((long long)in_sizes[i] > w_sz) { w_sz = in_sizes[i]; w_idx = i; }
    }
    W = (const float*)d_in[w_idx];
    for (int i = 0; i < n_in; i++) {
        if (i == w_idx) continue;
        if (in_sizes[i] == SHARDS * D_MODEL) b = (const float*)d_in[i];
        else { x = d_in[i]; n_tok = in_sizes[i]; }
    }

    float* out = (float*)d_out;

    dim3 grid(N_CHUNKS, (n_tok + TOK_PER_BLK - 1) / TOK_PER_BLK);
    fused_gather_kernel<<<grid, THREADS>>>((const int*)x, W, b, out, n_tok);
}